// round 15
// baseline (speedup 1.0000x reference)
#include <cuda_runtime.h>
#include <cuda_fp16.h>
#include <math.h>

#define BATCH 4
#define SEQ   2048
#define DM    1024
#define NH    16
#define DH    64
#define MTOT  (BATCH*SEQ)
#define OUT_ELEMS ((size_t)MTOT*DM)

__device__ float g_q[BATCH*NH*SEQ*DH];   // [b,h,s,d] raw fp32
__device__ float g_k[BATCH*NH*SEQ*DH];   // [b,h,s,d'] tf32, d low-3 bits permuted
__device__ float g_v[BATCH*NH*SEQ*DH];   // [b,h,d,s'] tf32, s low-3 bits permuted (V^T)
__device__ float g_ctx[MTOT*DM];
__device__ float g_fc[MTOT*DM];
__device__ __half g_e[(size_t)BATCH*NH*SEQ*SEQ];   // unnormalized exp(s)/16

__device__ __forceinline__ unsigned f2tf(float x) {
    unsigned r;
    asm("cvt.rna.tf32.f32 %0, %1;" : "=r"(r) : "f"(x));
    return r;
}

__device__ __forceinline__ void mma8(float* c, const unsigned* a, unsigned b0, unsigned b1) {
    asm volatile(
        "mma.sync.aligned.m16n8k8.row.col.f32.tf32.tf32.f32 "
        "{%0,%1,%2,%3},{%4,%5,%6,%7},{%8,%9},{%0,%1,%2,%3};"
        : "+f"(c[0]), "+f"(c[1]), "+f"(c[2]), "+f"(c[3])
        : "r"(a[0]), "r"(a[1]), "r"(a[2]), "r"(a[3]), "r"(b0), "r"(b1));
}

__device__ __forceinline__ void cpasync16(unsigned saddr, const void* g) {
    asm volatile("cp.async.cg.shared.global [%0], [%1], 16;" :: "r"(saddr), "l"(g));
}
__device__ __forceinline__ void cpasync_commit() {
    asm volatile("cp.async.commit_group;");
}
__device__ __forceinline__ void cpasync_wait0() {
    asm volatile("cp.async.wait_group 0;");
}

// permute low 3 bits: x = tig + 4h (tig<4) -> tig*2 + h
__device__ __forceinline__ int perm8(int x) {
    return (x & ~7) | ((x & 3) << 1) | ((x >> 2) & 1);
}

// ---------------------------------------------------------------------------
// Dense GEMM: C = X[M,K] @ W[N,K]^T, tf32 mma, CTA 128x128, BK=16,
// double-buffered smem with register prefetch.
// mode 0: scatter to [B,H,S,Dh] (Q); mode 1: +residual row-major (FC);
// mode 3: scatter to [B,H,S,Dh'] tf32-quantized, dh-permuted (K);
// mode 4: scatter to [B,H,Dh,S'] tf32-quantized, transposed + s-permuted (V).
// ---------------------------------------------------------------------------
#define KPAD 20

__global__ void __launch_bounds__(256, 2)
gemm_tf32(const float* __restrict__ X, const float* __restrict__ W,
          const float* __restrict__ resid, float* __restrict__ Y, int mode)
{
    extern __shared__ unsigned gsm[];
    unsigned (*As)[128][KPAD] = (unsigned(*)[128][KPAD])gsm;
    unsigned (*Bs)[128][KPAD] = (unsigned(*)[128][KPAD])(gsm + 2*128*KPAD);

    const int tid  = threadIdx.x;
    const int lane = tid & 31;
    const int warp = tid >> 5;
    const int warpM = warp >> 1;
    const int warpN = warp & 1;
    const int gid = lane >> 2;
    const int tig = lane & 3;

    const int ms = blockIdx.y * 128;
    const int ns = blockIdx.x * 128;
    const int lr = tid >> 2;
    const int lc = (tid & 3) * 4;

    float acc[2][8][4];
#pragma unroll
    for (int mt = 0; mt < 2; mt++)
#pragma unroll
        for (int nt = 0; nt < 8; nt++)
#pragma unroll
            for (int i = 0; i < 4; i++) acc[mt][nt][i] = 0.f;

    float4 px[2], pw[2];
#pragma unroll
    for (int h = 0; h < 2; h++) {
        int r = lr + h * 64;
        px[h] = *(const float4*)&X[(size_t)(ms + r) * DM + lc];
        pw[h] = *(const float4*)&W[(size_t)(ns + r) * DM + lc];
    }
#pragma unroll
    for (int h = 0; h < 2; h++) {
        int r = lr + h * 64;
        As[0][r][lc+0] = f2tf(px[h].x); As[0][r][lc+1] = f2tf(px[h].y);
        As[0][r][lc+2] = f2tf(px[h].z); As[0][r][lc+3] = f2tf(px[h].w);
        Bs[0][r][lc+0] = f2tf(pw[h].x); Bs[0][r][lc+1] = f2tf(pw[h].y);
        Bs[0][r][lc+2] = f2tf(pw[h].z); Bs[0][r][lc+3] = f2tf(pw[h].w);
    }
    __syncthreads();

    int buf = 0;
    for (int k0 = 0; k0 < DM; k0 += 16, buf ^= 1) {
        float4 nx[2], nw[2];
        const bool more = (k0 + 16 < DM);
        if (more) {
#pragma unroll
            for (int h = 0; h < 2; h++) {
                int r = lr + h * 64;
                nx[h] = *(const float4*)&X[(size_t)(ms + r) * DM + k0 + 16 + lc];
                nw[h] = *(const float4*)&W[(size_t)(ns + r) * DM + k0 + 16 + lc];
            }
        }

#pragma unroll
        for (int ks = 0; ks < 2; ks++) {
            const int kc = ks * 8 + tig;
            unsigned a[2][4];
#pragma unroll
            for (int mt = 0; mt < 2; mt++) {
                int base = warpM * 32 + mt * 16;
                a[mt][0] = As[buf][base + gid][kc];
                a[mt][1] = As[buf][base + gid + 8][kc];
                a[mt][2] = As[buf][base + gid][kc + 4];
                a[mt][3] = As[buf][base + gid + 8][kc + 4];
            }
#pragma unroll
            for (int nt = 0; nt < 8; nt++) {
                int cb = warpN * 64 + nt * 8 + gid;
                unsigned b0 = Bs[buf][cb][kc];
                unsigned b1 = Bs[buf][cb][kc + 4];
                mma8(acc[0][nt], a[0], b0, b1);
                mma8(acc[1][nt], a[1], b0, b1);
            }
        }

        if (more) {
            int nb = buf ^ 1;
#pragma unroll
            for (int h = 0; h < 2; h++) {
                int r = lr + h * 64;
                As[nb][r][lc+0] = f2tf(nx[h].x); As[nb][r][lc+1] = f2tf(nx[h].y);
                As[nb][r][lc+2] = f2tf(nx[h].z); As[nb][r][lc+3] = f2tf(nx[h].w);
                Bs[nb][r][lc+0] = f2tf(nw[h].x); Bs[nb][r][lc+1] = f2tf(nw[h].y);
                Bs[nb][r][lc+2] = f2tf(nw[h].z); Bs[nb][r][lc+3] = f2tf(nw[h].w);
            }
        }
        __syncthreads();
    }

#pragma unroll
    for (int mt = 0; mt < 2; mt++) {
#pragma unroll
        for (int nt = 0; nt < 8; nt++) {
#pragma unroll
            for (int i = 0; i < 4; i++) {
                int m = ms + warpM * 32 + mt * 16 + gid + (i >> 1) * 8;
                int n = ns + warpN * 64 + nt * 8 + tig * 2 + (i & 1);
                float v = acc[mt][nt][i];
                if (mode == 0) {
                    int b_ = m >> 11, s_ = m & 2047;
                    int h = n >> 6, dh = n & 63;
                    Y[(((size_t)(b_*NH + h))*SEQ + s_)*DH + dh] = v;
                } else if (mode == 3) {
                    int b_ = m >> 11, s_ = m & 2047;
                    int h = n >> 6, dh = n & 63;
                    Y[(((size_t)(b_*NH + h))*SEQ + s_)*DH + perm8(dh)] = __uint_as_float(f2tf(v));
                } else if (mode == 4) {
                    int b_ = m >> 11, s_ = m & 2047;
                    int h = n >> 6, dh = n & 63;
                    Y[(((size_t)(b_*NH + h))*DH + dh)*SEQ + ((s_ & ~7) | ((s_&3)<<1) | ((s_>>2)&1))]
                        = __uint_as_float(f2tf(v));
                } else {
                    Y[(size_t)m * DM + n] = v + resid[(size_t)m * DM + n];
                }
            }
        }
    }
}

// ---------------------------------------------------------------------------
// Flash-style attention. CTA = (b,h, 64 q rows), 256 thr, 8 warps =
// 4 q-groups x 2 key-slices. K [s][d'] and V^T [d][s'] pre-quantized tf32,
// pair-interleaved low-3-bit permutations -> all mma B fragments are LDS.64.
// Smem strides 72 (== 8 mod 32 banks) -> LDS.64 phases conflict-free.
// Double-buffered 64-key tiles via cp.async. Split hi/lo QK accumulators.
// e dumped fp16/16 coalesced; end sweep normalizes into attn_out.
// ---------------------------------------------------------------------------
#define AKT   64
#define NTIL  (SEQ/AKT)                    // 32
#define SKSTR 72
#define SVSTR 72
#define SESTR 36
#define KBUF  (AKT*SKSTR)                  // 4608
#define VBUF  (DH*SVSTR)                   // 4608
#define SM_K   0
#define SM_V   (2*KBUF)                    // 9216
#define SM_E   (SM_V + 2*VBUF)             // 18432
#define SM_SUM (SM_E + 8*16*SESTR)         // 23040
#define SM_INV (SM_SUM + 128)              // 23168
#define SM_ATT (SM_INV + 64)               // 23232 floats = 92928 B

__global__ void __launch_bounds__(256, 2)
attn_kernel(const float* __restrict__ gq, const float* __restrict__ gk,
            const float* __restrict__ gv, float* __restrict__ attn_out,
            float* __restrict__ ctx, __half* __restrict__ gE)
{
    extern __shared__ float sm[];
    float* sE   = sm + SM_E;
    float* sSum = sm + SM_SUM;
    float* sInv = sm + SM_INV;

    const int tid  = threadIdx.x;
    const int lane = tid & 31;
    const int w    = tid >> 5;       // 0..7
    const int gid  = lane >> 2;      // 0..7
    const int tig  = lane & 3;       // 0..3
    const int qg   = w >> 1;         // 0..3
    const int ns   = w & 1;          // 0..1

    const int bid = blockIdx.x;
    const int qt  = bid & 31;
    const int bh  = bid >> 5;
    const int q0  = qt * 64;

    const float* Qb = gq + (size_t)bh * SEQ * DH;
    const float* Kb = gk + (size_t)bh * SEQ * DH;    // [s][d'] rows of 64
    const float* Vb = gv + (size_t)bh * DH * SEQ;    // [d][s'] rows of 2048

    const unsigned sbase = (unsigned)__cvta_generic_to_shared(sm);
    float* sEw = sE + w * 16 * SESTR;

    // staging indices: per thread 4 K-chunks + 4 V-chunks of 16B per tile
    const int str = tid >> 4;            // 0..15
    const int stc = (tid & 15) << 2;     // 0..60 step 4

    // ---- prologue: stage tile 0 ----
#pragma unroll
    for (int i = 0; i < 4; i++) {
        int r = str + i * 16;
        cpasync16(sbase + (SM_K + r*SKSTR + stc)*4, Kb + (size_t)r*DH + stc);
        cpasync16(sbase + (SM_V + r*SVSTR + stc)*4, Vb + (size_t)r*SEQ + stc);
    }
    cpasync_commit();

    // ---- Q fragments (hi/lo tf32), scale folded ----
    unsigned qhi[8][4], qlo[8][4];
    {
        const float* Qr0 = Qb + (size_t)(q0 + qg*16 + gid) * DH;
        const float* Qr1 = Qr0 + (size_t)8 * DH;
#pragma unroll
        for (int kc = 0; kc < 8; kc++) {
            float v[4];
            v[0] = Qr0[kc*8 + tig]     * 0.125f;
            v[1] = Qr1[kc*8 + tig]     * 0.125f;
            v[2] = Qr0[kc*8 + tig + 4] * 0.125f;
            v[3] = Qr1[kc*8 + tig + 4] * 0.125f;
#pragma unroll
            for (int i = 0; i < 4; i++) {
                unsigned h = f2tf(v[i]);
                qhi[kc][i] = h;
                qlo[kc][i] = f2tf(v[i] - __uint_as_float(h));
            }
        }
    }

    float rsum0 = 0.f, rsum1 = 0.f;
    float acc2[8][4];
#pragma unroll
    for (int nd = 0; nd < 8; nd++)
#pragma unroll
        for (int i = 0; i < 4; i++) acc2[nd][i] = 0.f;

    // ================= main pass =================
    for (int t = 0; t < NTIL; t++) {
        const int buf = t & 1;
        const float* sKb = sm + SM_K + buf*KBUF;
        const float* sVb = sm + SM_V + buf*VBUF;

        cpasync_wait0();
        __syncthreads();

        if (t + 1 < NTIL) {
            const int nb = (t + 1) & 1;
            const float* Kn = Kb + (size_t)(t+1)*AKT*DH;
            const float* Vn = Vb + (size_t)(t+1)*AKT;
#pragma unroll
            for (int i = 0; i < 4; i++) {
                int r = str + i * 16;
                cpasync16(sbase + (SM_K + nb*KBUF + r*SKSTR + stc)*4, Kn + (size_t)r*DH + stc);
                cpasync16(sbase + (SM_V + nb*VBUF + r*SVSTR + stc)*4, Vn + (size_t)r*SEQ + stc);
            }
            cpasync_commit();
        }

        // ---- QK + exp + e staging, split hi/lo accumulators ----
#pragma unroll
        for (int n8 = 0; n8 < 4; n8++) {
            const int n0 = ns * 32 + n8 * 8;
            float ah[4] = {0.f, 0.f, 0.f, 0.f};
            float al[4] = {0.f, 0.f, 0.f, 0.f};
#pragma unroll
            for (int kc = 0; kc < 8; kc++) {
                float2 b = *(const float2*)&sKb[(n0 + gid)*SKSTR + kc*8 + tig*2];
                mma8(ah, qhi[kc], __float_as_uint(b.x), __float_as_uint(b.y));
                mma8(al, qlo[kc], __float_as_uint(b.x), __float_as_uint(b.y));
            }
            float a0 = __expf(ah[0] + al[0]);
            float a1 = __expf(ah[1] + al[1]);
            float a2 = __expf(ah[2] + al[2]);
            float a3 = __expf(ah[3] + al[3]);
            rsum0 += a0 + a1;
            rsum1 += a2 + a3;
            float2 e0 = make_float2(__uint_as_float(f2tf(a0)), __uint_as_float(f2tf(a1)));
            float2 e1 = make_float2(__uint_as_float(f2tf(a2)), __uint_as_float(f2tf(a3)));
            *(float2*)&sEw[gid*SESTR + n8*8 + 2*tig]     = e0;
            *(float2*)&sEw[(gid+8)*SESTR + n8*8 + 2*tig] = e1;
        }
        __syncwarp();

        // ---- PV over this warp's 32 keys (V^T tile, permuted cols) ----
#pragma unroll
        for (int k8 = 0; k8 < 4; k8++) {
            unsigned a[4];
            a[0] = __float_as_uint(sEw[gid*SESTR + k8*8 + tig]);
            a[1] = __float_as_uint(sEw[(gid+8)*SESTR + k8*8 + tig]);
            a[2] = __float_as_uint(sEw[gid*SESTR + k8*8 + tig + 4]);
            a[3] = __float_as_uint(sEw[(gid+8)*SESTR + k8*8 + tig + 4]);
            const int kc2 = ns*32 + k8*8 + tig*2;
#pragma unroll
            for (int nd = 0; nd < 8; nd++) {
                float2 b = *(const float2*)&sVb[(nd*8 + gid)*SVSTR + kc2];
                mma8(acc2[nd], a, __float_as_uint(b.x), __float_as_uint(b.y));
            }
        }

        // ---- e dump: sEw (16x32) -> gE fp16 (scaled 1/16), coalesced ----
        {
            const int r0 = lane >> 2;            // 0..7
            const int c8 = (lane & 3) * 8;       // 0,8,16,24
#pragma unroll
            for (int rg = 0; rg < 16; rg += 8) {
                const float* s = &sEw[(rg + r0)*SESTR + c8];
                float4 v0 = *(const float4*)&s[0];
                float4 v1 = *(const float4*)&s[4];
                __half2 h0 = __floats2half2_rn(v0.x*0.0625f, v0.y*0.0625f);
                __half2 h1 = __floats2half2_rn(v0.z*0.0625f, v0.w*0.0625f);
                __half2 h2 = __floats2half2_rn(v1.x*0.0625f, v1.y*0.0625f);
                __half2 h3 = __floats2half2_rn(v1.z*0.0625f, v1.w*0.0625f);
                uint4 pk;
                pk.x = *(const unsigned*)&h0;
                pk.y = *(const unsigned*)&h1;
                pk.z = *(const unsigned*)&h2;
                pk.w = *(const unsigned*)&h3;
                *(uint4*)&gE[((size_t)bh*SEQ + q0 + qg*16 + rg + r0)*SEQ
                             + t*AKT + ns*32 + c8] = pk;
            }
        }
    }

    // ---- row-sum reduction ----
    rsum0 += __shfl_xor_sync(0xffffffffu, rsum0, 1);
    rsum0 += __shfl_xor_sync(0xffffffffu, rsum0, 2);
    rsum1 += __shfl_xor_sync(0xffffffffu, rsum1, 1);
    rsum1 += __shfl_xor_sync(0xffffffffu, rsum1, 2);
    if (tig == 0) {
        sSum[w*16 + gid]     = rsum0;
        sSum[w*16 + gid + 8] = rsum1;
    }
    __syncthreads();
    if (tid < 64) {
        int qgq = tid >> 4, r = tid & 15;
        float s = sSum[(qgq*2)*16 + r] + sSum[(qgq*2 + 1)*16 + r];
        sInv[tid] = 1.f / s;
    }
    // ---- O partial stage into retired K/V buffer region (stride 68) ----
    {
        float* sOw = sm + w * 1088;    // 16*68 per warp, 8704 floats total
#pragma unroll
        for (int nd = 0; nd < 8; nd++) {
            *(float2*)&sOw[gid*68 + nd*8 + 2*tig]     = make_float2(acc2[nd][0], acc2[nd][1]);
            *(float2*)&sOw[(gid+8)*68 + nd*8 + 2*tig] = make_float2(acc2[nd][2], acc2[nd][3]);
        }
    }
    __syncthreads();

    // ---- ctx write ----
    {
        const int b_ = bh >> 4, h = bh & 15;
#pragma unroll
        for (int i = 0; i < 16; i++) {
            int idx = tid + i * 256;             // 0..4095
            int q = idx >> 6, dh = idx & 63;
            int qgi = q >> 4, r = q & 15;
            float o = sm[(qgi*2)*1088 + r*68 + dh]
                    + sm[(qgi*2 + 1)*1088 + r*68 + dh];
            o *= sInv[q];
            ctx[((size_t)(b_*SEQ + q0 + q))*DM + h*DH + dh] = o;
        }
    }

    // ---- normalization sweep: p = e_fp16 * (inv*16) -> gmem attn ----
    {
        const uint4* src = (const uint4*)(gE + ((size_t)bh*SEQ + q0)*SEQ);
        float* dst = attn_out + ((size_t)bh*SEQ + q0)*SEQ;
#pragma unroll 4
        for (int i = tid; i < 64*SEQ/8; i += 256) {   // 16384 uint4
            float inv = sInv[i >> 8] * 16.f;           // (i*8) >> 11
            uint4 raw = src[i];
            float2 f0 = __half22float2(*(const __half2*)&raw.x);
            float2 f1 = __half22float2(*(const __half2*)&raw.y);
            float2 f2 = __half22float2(*(const __half2*)&raw.z);
            float2 f3 = __half22float2(*(const __half2*)&raw.w);
            float4 p0 = make_float4(f0.x*inv, f0.y*inv, f1.x*inv, f1.y*inv);
            float4 p1 = make_float4(f2.x*inv, f2.y*inv, f3.x*inv, f3.y*inv);
            *(float4*)&dst[i*8]     = p0;
            *(float4*)&dst[i*8 + 4] = p1;
        }
    }
}

// ---------------------------------------------------------------------------
__global__ void ln_kernel(const float* __restrict__ x, float* __restrict__ out)
{
    __shared__ float red[16];
    const int row = blockIdx.x, tid = threadIdx.x;
    const float* xr = x + (size_t)row * DM;
    float4 d = ((const float4*)xr)[tid];
    float s  = d.x + d.y + d.z + d.w;
    float sq = d.x*d.x + d.y*d.y + d.z*d.z + d.w*d.w;
#pragma unroll
    for (int o = 16; o; o >>= 1) {
        s  += __shfl_xor_sync(0xffffffffu, s,  o);
        sq += __shfl_xor_sync(0xffffffffu, sq, o);
    }
    int warp = tid >> 5, lane = tid & 31;
    if (lane == 0) { red[warp] = s; red[warp + 8] = sq; }
    __syncthreads();
    float st = 0.f, sqt = 0.f;
#pragma unroll
    for (int i = 0; i < 8; i++) { st += red[i]; sqt += red[8 + i]; }
    float mean = st * (1.f/1024.f);
    float var  = sqt * (1.f/1024.f) - mean * mean;
    float rstd = rsqrtf(var + 1e-5f);
    float4 o;
    o.x = (d.x - mean) * rstd; o.y = (d.y - mean) * rstd;
    o.z = (d.z - mean) * rstd; o.w = (d.w - mean) * rstd;
    ((float4*)(out + (size_t)row * DM))[tid] = o;
}

// ---------------------------------------------------------------------------
extern "C" void kernel_launch(void* const* d_in, const int* in_sizes, int n_in,
                              void* d_out, int out_size)
{
    const float* iq  = (const float*)d_in[0];
    const float* ik  = (const float*)d_in[1];
    const float* iv  = (const float*)d_in[2];
    const float* wq  = (const float*)d_in[3];
    const float* wk  = (const float*)d_in[4];
    const float* wv  = (const float*)d_in[5];
    const float* wfc = (const float*)d_in[6];

    float* out  = (float*)d_out;
    float* attn = out + OUT_ELEMS;

    float *gq, *gk, *gv, *gctx, *gfc;
    __half* ge;
    cudaGetSymbolAddress((void**)&gq,   g_q);
    cudaGetSymbolAddress((void**)&gk,   g_k);
    cudaGetSymbolAddress((void**)&gv,   g_v);
    cudaGetSymbolAddress((void**)&gctx, g_ctx);
    cudaGetSymbolAddress((void**)&gfc,  g_fc);
    cudaGetSymbolAddress((void**)&ge,   g_e);

    dim3 gg(DM/128, MTOT/128);
    size_t gemm_smem = (size_t)4 * 128 * KPAD * sizeof(unsigned);
    cudaFuncSetAttribute(gemm_tf32, cudaFuncAttributeMaxDynamicSharedMemorySize, (int)gemm_smem);

    gemm_tf32<<<gg, 256, gemm_smem>>>(iq, wq, nullptr, gq, 0);
    gemm_tf32<<<gg, 256, gemm_smem>>>(ik, wk, nullptr, gk, 3);
    gemm_tf32<<<gg, 256, gemm_smem>>>(iv, wv, nullptr, gv, 4);

    size_t smem = (size_t)SM_ATT * sizeof(float);   // 92928 B
    cudaFuncSetAttribute(attn_kernel, cudaFuncAttributeMaxDynamicSharedMemorySize, (int)smem);
    attn_kernel<<<BATCH*NH*(SEQ/64), 256, smem>>>(gq, gk, gv, attn, gctx, ge);

    gemm_tf32<<<gg, 256, gemm_smem>>>(gctx, wfc, iq, gfc, 1);
    ln_kernel<<<MTOT, 256>>>(gfc, out);
}

// round 16
// speedup vs baseline: 1.4854x; 1.4854x over previous
#include <cuda_runtime.h>
#include <cuda_fp16.h>
#include <math.h>

#define BATCH 4
#define SEQ   2048
#define DM    1024
#define NH    16
#define DH    64
#define MTOT  (BATCH*SEQ)
#define OUT_ELEMS ((size_t)MTOT*DM)

__device__ float g_q[BATCH*NH*SEQ*DH];   // [b,h,s,d] raw fp32
__device__ float g_k[BATCH*NH*SEQ*DH];   // [b,h,s,d] tf32-quantized values
__device__ float g_v[BATCH*NH*SEQ*DH];   // [b,h,s,d] tf32-quantized values
__device__ float g_ctx[MTOT*DM];
__device__ float g_fc[MTOT*DM];
__device__ __half g_e[(size_t)BATCH*NH*SEQ*SEQ];   // unnormalized exp(s)/16

__device__ __forceinline__ unsigned f2tf(float x) {
    unsigned r;
    asm("cvt.rna.tf32.f32 %0, %1;" : "=r"(r) : "f"(x));
    return r;
}

__device__ __forceinline__ void mma8(float* c, const unsigned* a, unsigned b0, unsigned b1) {
    asm volatile(
        "mma.sync.aligned.m16n8k8.row.col.f32.tf32.tf32.f32 "
        "{%0,%1,%2,%3},{%4,%5,%6,%7},{%8,%9},{%0,%1,%2,%3};"
        : "+f"(c[0]), "+f"(c[1]), "+f"(c[2]), "+f"(c[3])
        : "r"(a[0]), "r"(a[1]), "r"(a[2]), "r"(a[3]), "r"(b0), "r"(b1));
}

__device__ __forceinline__ void cpasync16(unsigned saddr, const void* g) {
    asm volatile("cp.async.cg.shared.global [%0], [%1], 16;" :: "r"(saddr), "l"(g));
}
__device__ __forceinline__ void cpasync_commit() {
    asm volatile("cp.async.commit_group;");
}
__device__ __forceinline__ void cpasync_wait0() {
    asm volatile("cp.async.wait_group 0;");
}

// ---------------------------------------------------------------------------
// Dense GEMM body: C = X[M,K] @ W[N,K]^T, tf32 mma, CTA 128x128, BK=16,
// double-buffered smem with register prefetch.
// mode 0: scatter to [B,H,S,Dh]; mode 1: +residual row-major;
// mode 3: scatter to [B,H,S,Dh] with rna-tf32 quantization (K, V).
// ---------------------------------------------------------------------------
#define KPAD 20

__device__ __forceinline__ void gemm_body(
    const float* __restrict__ X, const float* __restrict__ W,
    const float* __restrict__ resid, float* __restrict__ Y, int mode,
    unsigned* gsm)
{
    unsigned (*As)[128][KPAD] = (unsigned(*)[128][KPAD])gsm;
    unsigned (*Bs)[128][KPAD] = (unsigned(*)[128][KPAD])(gsm + 2*128*KPAD);

    const int tid  = threadIdx.x;
    const int lane = tid & 31;
    const int warp = tid >> 5;
    const int warpM = warp >> 1;
    const int warpN = warp & 1;
    const int gid = lane >> 2;
    const int tig = lane & 3;

    const int ms = blockIdx.y * 128;
    const int ns = blockIdx.x * 128;
    const int lr = tid >> 2;
    const int lc = (tid & 3) * 4;

    float acc[2][8][4];
#pragma unroll
    for (int mt = 0; mt < 2; mt++)
#pragma unroll
        for (int nt = 0; nt < 8; nt++)
#pragma unroll
            for (int i = 0; i < 4; i++) acc[mt][nt][i] = 0.f;

    float4 px[2], pw[2];
#pragma unroll
    for (int h = 0; h < 2; h++) {
        int r = lr + h * 64;
        px[h] = *(const float4*)&X[(size_t)(ms + r) * DM + lc];
        pw[h] = *(const float4*)&W[(size_t)(ns + r) * DM + lc];
    }
#pragma unroll
    for (int h = 0; h < 2; h++) {
        int r = lr + h * 64;
        As[0][r][lc+0] = f2tf(px[h].x); As[0][r][lc+1] = f2tf(px[h].y);
        As[0][r][lc+2] = f2tf(px[h].z); As[0][r][lc+3] = f2tf(px[h].w);
        Bs[0][r][lc+0] = f2tf(pw[h].x); Bs[0][r][lc+1] = f2tf(pw[h].y);
        Bs[0][r][lc+2] = f2tf(pw[h].z); Bs[0][r][lc+3] = f2tf(pw[h].w);
    }
    __syncthreads();

    int buf = 0;
    for (int k0 = 0; k0 < DM; k0 += 16, buf ^= 1) {
        float4 nx[2], nw[2];
        const bool more = (k0 + 16 < DM);
        if (more) {
#pragma unroll
            for (int h = 0; h < 2; h++) {
                int r = lr + h * 64;
                nx[h] = *(const float4*)&X[(size_t)(ms + r) * DM + k0 + 16 + lc];
                nw[h] = *(const float4*)&W[(size_t)(ns + r) * DM + k0 + 16 + lc];
            }
        }

#pragma unroll
        for (int ks = 0; ks < 2; ks++) {
            const int kc = ks * 8 + tig;
            unsigned a[2][4];
#pragma unroll
            for (int mt = 0; mt < 2; mt++) {
                int base = warpM * 32 + mt * 16;
                a[mt][0] = As[buf][base + gid][kc];
                a[mt][1] = As[buf][base + gid + 8][kc];
                a[mt][2] = As[buf][base + gid][kc + 4];
                a[mt][3] = As[buf][base + gid + 8][kc + 4];
            }
#pragma unroll
            for (int nt = 0; nt < 8; nt++) {
                int cb = warpN * 64 + nt * 8 + gid;
                unsigned b0 = Bs[buf][cb][kc];
                unsigned b1 = Bs[buf][cb][kc + 4];
                mma8(acc[0][nt], a[0], b0, b1);
                mma8(acc[1][nt], a[1], b0, b1);
            }
        }

        if (more) {
            int nb = buf ^ 1;
#pragma unroll
            for (int h = 0; h < 2; h++) {
                int r = lr + h * 64;
                As[nb][r][lc+0] = f2tf(nx[h].x); As[nb][r][lc+1] = f2tf(nx[h].y);
                As[nb][r][lc+2] = f2tf(nx[h].z); As[nb][r][lc+3] = f2tf(nx[h].w);
                Bs[nb][r][lc+0] = f2tf(nw[h].x); Bs[nb][r][lc+1] = f2tf(nw[h].y);
                Bs[nb][r][lc+2] = f2tf(nw[h].z); Bs[nb][r][lc+3] = f2tf(nw[h].w);
            }
        }
        __syncthreads();
    }

#pragma unroll
    for (int mt = 0; mt < 2; mt++) {
#pragma unroll
        for (int nt = 0; nt < 8; nt++) {
#pragma unroll
            for (int i = 0; i < 4; i++) {
                int m = ms + warpM * 32 + mt * 16 + gid + (i >> 1) * 8;
                int n = ns + warpN * 64 + nt * 8 + tig * 2 + (i & 1);
                float v = acc[mt][nt][i];
                if (mode == 0) {
                    int b_ = m >> 11, s_ = m & 2047;
                    int h = n >> 6, dh = n & 63;
                    Y[(((size_t)(b_*NH + h))*SEQ + s_)*DH + dh] = v;
                } else if (mode == 3) {
                    int b_ = m >> 11, s_ = m & 2047;
                    int h = n >> 6, dh = n & 63;
                    Y[(((size_t)(b_*NH + h))*SEQ + s_)*DH + dh] = __uint_as_float(f2tf(v));
                } else {
                    Y[(size_t)m * DM + n] = v + resid[(size_t)m * DM + n];
                }
            }
        }
    }
}

// FC GEMM (mode 1)
__global__ void __launch_bounds__(256, 2)
gemm_tf32(const float* __restrict__ X, const float* __restrict__ W,
          const float* __restrict__ resid, float* __restrict__ Y, int mode)
{
    extern __shared__ unsigned gsm[];
    gemm_body(X, W, resid, Y, mode, gsm);
}

// Merged Q/K/V projections: blockIdx.z selects the problem. One launch of
// 1536 CTAs packs the wave tails that three 512-CTA launches would waste.
struct QKVArgs {
    const float* X[3];
    const float* W[3];
    float*       Y[3];
    int          mode[3];
};

__global__ void __launch_bounds__(256, 2)
gemm_qkv(QKVArgs args)
{
    extern __shared__ unsigned gsm[];
    const int z = blockIdx.z;
    gemm_body(args.X[z], args.W[z], nullptr, args.Y[z], args.mode[z], gsm);
}

// ---------------------------------------------------------------------------
// Flash-style attention (R12 configuration — best measured).
// CTA = (b,h, 64 q rows), 256 thr, 8 warps = 4 q-groups x 2 key-slices.
// K/V gmem values pre-quantized tf32 -> raw cp.async staging exact.
// Double-buffered 64-key tiles, one sync/tile. Split hi/lo QK accumulators.
// e stored tf32 in smem for PV, dumped fp16/16 coalesced to g_e; end sweep
// normalizes into attn_out.
// ---------------------------------------------------------------------------
#define AKT   64
#define NTIL  (SEQ/AKT)                    // 32
#define SKSTR 68
#define SVSTR 72
#define SESTR 36
#define KBUF  (AKT*SKSTR)                  // 4352
#define VBUF  (AKT*SVSTR)                  // 4608
#define SM_K   0
#define SM_V   (2*KBUF)                    // 8704
#define SM_E   (SM_V + 2*VBUF)             // 17920
#define SM_SUM (SM_E + 8*16*SESTR)         // 22528
#define SM_INV (SM_SUM + 128)              // 22656
#define SM_ATT (SM_INV + 64)               // 22720 floats = 90880 B

__global__ void __launch_bounds__(256, 2)
attn_kernel(const float* __restrict__ gq, const float* __restrict__ gk,
            const float* __restrict__ gv, float* __restrict__ attn_out,
            float* __restrict__ ctx, __half* __restrict__ gE)
{
    extern __shared__ float sm[];
    float* sE   = sm + SM_E;
    float* sSum = sm + SM_SUM;
    float* sInv = sm + SM_INV;

    const int tid  = threadIdx.x;
    const int lane = tid & 31;
    const int w    = tid >> 5;       // 0..7
    const int gid  = lane >> 2;      // 0..7
    const int tig  = lane & 3;       // 0..3
    const int qg   = w >> 1;         // 0..3
    const int ns   = w & 1;          // 0..1

    const int bid = blockIdx.x;
    const int qt  = bid & 31;
    const int bh  = bid >> 5;
    const int q0  = qt * 64;

    const float* Qb = gq + (size_t)bh * SEQ * DH;
    const float* Kb = gk + (size_t)bh * SEQ * DH;
    const float* Vb = gv + (size_t)bh * SEQ * DH;

    const unsigned sbase = (unsigned)__cvta_generic_to_shared(sm);
    float* sEw = sE + w * 16 * SESTR;

    // staging indices: per thread 4 K + 4 V cp.asyncs of 16B per tile
    const int str = tid >> 4;            // 0..15
    const int stc = (tid & 15) << 2;     // 0..60 step 4

    // ---- prologue: stage tile 0 ----
#pragma unroll
    for (int i = 0; i < 4; i++) {
        int r = str + i * 16;
        cpasync16(sbase + (SM_K + r*SKSTR + stc)*4, Kb + (size_t)r*DH + stc);
        cpasync16(sbase + (SM_V + r*SVSTR + stc)*4, Vb + (size_t)r*DH + stc);
    }
    cpasync_commit();

    // ---- Q fragments (hi/lo tf32), scale folded ----
    unsigned qhi[8][4], qlo[8][4];
    {
        const float* Qr0 = Qb + (size_t)(q0 + qg*16 + gid) * DH;
        const float* Qr1 = Qr0 + (size_t)8 * DH;
#pragma unroll
        for (int kc = 0; kc < 8; kc++) {
            float v[4];
            v[0] = Qr0[kc*8 + tig]     * 0.125f;
            v[1] = Qr1[kc*8 + tig]     * 0.125f;
            v[2] = Qr0[kc*8 + tig + 4] * 0.125f;
            v[3] = Qr1[kc*8 + tig + 4] * 0.125f;
#pragma unroll
            for (int i = 0; i < 4; i++) {
                unsigned h = f2tf(v[i]);
                qhi[kc][i] = h;
                qlo[kc][i] = f2tf(v[i] - __uint_as_float(h));
            }
        }
    }

    float rsum0 = 0.f, rsum1 = 0.f;
    float acc2[8][4];
#pragma unroll
    for (int nd = 0; nd < 8; nd++)
#pragma unroll
        for (int i = 0; i < 4; i++) acc2[nd][i] = 0.f;

    // ================= main pass =================
    for (int t = 0; t < NTIL; t++) {
        const int buf = t & 1;
        const float* sKb = sm + SM_K + buf*KBUF;
        const float* sVb = sm + SM_V + buf*VBUF;

        cpasync_wait0();
        __syncthreads();

        if (t + 1 < NTIL) {
            const int nb = (t + 1) & 1;
            const float* Kn = Kb + (size_t)(t+1)*AKT*DH;
            const float* Vn = Vb + (size_t)(t+1)*AKT*DH;
#pragma unroll
            for (int i = 0; i < 4; i++) {
                int r = str + i * 16;
                cpasync16(sbase + (SM_K + nb*KBUF + r*SKSTR + stc)*4, Kn + (size_t)r*DH + stc);
                cpasync16(sbase + (SM_V + nb*VBUF + r*SVSTR + stc)*4, Vn + (size_t)r*DH + stc);
            }
            cpasync_commit();
        }

        // ---- QK + exp + e staging (warp-local), split hi/lo accumulators ----
#pragma unroll
        for (int n8 = 0; n8 < 4; n8++) {
            const int n0 = ns * 32 + n8 * 8;
            float ah[4] = {0.f, 0.f, 0.f, 0.f};
            float al[4] = {0.f, 0.f, 0.f, 0.f};
#pragma unroll
            for (int kc = 0; kc < 8; kc++) {
                unsigned b0 = __float_as_uint(sKb[(n0 + gid)*SKSTR + kc*8 + tig]);
                unsigned b1 = __float_as_uint(sKb[(n0 + gid)*SKSTR + kc*8 + tig + 4]);
                mma8(ah, qhi[kc], b0, b1);
                mma8(al, qlo[kc], b0, b1);
            }
            float a0 = __expf(ah[0] + al[0]);
            float a1 = __expf(ah[1] + al[1]);
            float a2 = __expf(ah[2] + al[2]);
            float a3 = __expf(ah[3] + al[3]);
            rsum0 += a0 + a1;
            rsum1 += a2 + a3;
            sEw[gid*SESTR + n8*8 + 2*tig]       = __uint_as_float(f2tf(a0));
            sEw[gid*SESTR + n8*8 + 2*tig + 1]   = __uint_as_float(f2tf(a1));
            sEw[(gid+8)*SESTR + n8*8 + 2*tig]   = __uint_as_float(f2tf(a2));
            sEw[(gid+8)*SESTR + n8*8 + 2*tig+1] = __uint_as_float(f2tf(a3));
        }
        __syncwarp();

        // ---- PV over this warp's 32 keys ----
#pragma unroll
        for (int k8 = 0; k8 < 4; k8++) {
            unsigned a[4];
            a[0] = __float_as_uint(sEw[gid*SESTR + k8*8 + tig]);
            a[1] = __float_as_uint(sEw[(gid+8)*SESTR + k8*8 + tig]);
            a[2] = __float_as_uint(sEw[gid*SESTR + k8*8 + tig + 4]);
            a[3] = __float_as_uint(sEw[(gid+8)*SESTR + k8*8 + tig + 4]);
            const int kr = ns * 32 + k8 * 8;
#pragma unroll
            for (int nd = 0; nd < 8; nd++) {
                unsigned b0 = __float_as_uint(sVb[(kr + tig)*SVSTR + nd*8 + gid]);
                unsigned b1 = __float_as_uint(sVb[(kr + tig + 4)*SVSTR + nd*8 + gid]);
                mma8(acc2[nd], a, b0, b1);
            }
        }

        // ---- e dump: sEw (16x32) -> gE fp16 (scaled 1/16), coalesced ----
        {
            const int r0 = lane >> 2;            // 0..7
            const int c8 = (lane & 3) * 8;       // 0,8,16,24
#pragma unroll
            for (int rg = 0; rg < 16; rg += 8) {
                const float* s = &sEw[(rg + r0)*SESTR + c8];
                float4 v0 = *(const float4*)&s[0];
                float4 v1 = *(const float4*)&s[4];
                __half2 h0 = __floats2half2_rn(v0.x*0.0625f, v0.y*0.0625f);
                __half2 h1 = __floats2half2_rn(v0.z*0.0625f, v0.w*0.0625f);
                __half2 h2 = __floats2half2_rn(v1.x*0.0625f, v1.y*0.0625f);
                __half2 h3 = __floats2half2_rn(v1.z*0.0625f, v1.w*0.0625f);
                uint4 pk;
                pk.x = *(const unsigned*)&h0;
                pk.y = *(const unsigned*)&h1;
                pk.z = *(const unsigned*)&h2;
                pk.w = *(const unsigned*)&h3;
                *(uint4*)&gE[((size_t)bh*SEQ + q0 + qg*16 + rg + r0)*SEQ
                             + t*AKT + ns*32 + c8] = pk;
            }
        }
    }

    // ---- row-sum reduction ----
    rsum0 += __shfl_xor_sync(0xffffffffu, rsum0, 1);
    rsum0 += __shfl_xor_sync(0xffffffffu, rsum0, 2);
    rsum1 += __shfl_xor_sync(0xffffffffu, rsum1, 1);
    rsum1 += __shfl_xor_sync(0xffffffffu, rsum1, 2);
    if (tig == 0) {
        sSum[w*16 + gid]     = rsum0;
        sSum[w*16 + gid + 8] = rsum1;
    }
    __syncthreads();
    if (tid < 64) {
        int qgq = tid >> 4, r = tid & 15;
        float s = sSum[(qgq*2)*16 + r] + sSum[(qgq*2 + 1)*16 + r];
        sInv[tid] = 1.f / s;
    }
    // ---- O partial stage into retired K/V buffer region (stride 68) ----
    {
        float* sOw = sm + w * 1088;    // 16*68 per warp, 8704 floats total
#pragma unroll
        for (int nd = 0; nd < 8; nd++) {
            sOw[gid*68 + nd*8 + 2*tig]       = acc2[nd][0];
            sOw[gid*68 + nd*8 + 2*tig + 1]   = acc2[nd][1];
            sOw[(gid+8)*68 + nd*8 + 2*tig]   = acc2[nd][2];
            sOw[(gid+8)*68 + nd*8 + 2*tig+1] = acc2[nd][3];
        }
    }
    __syncthreads();

    // ---- ctx write ----
    {
        const int b_ = bh >> 4, h = bh & 15;
#pragma unroll
        for (int i = 0; i < 16; i++) {
            int idx = tid + i * 256;             // 0..4095
            int q = idx >> 6, dh = idx & 63;
            int qgi = q >> 4, r = q & 15;
            float o = sm[(qgi*2)*1088 + r*68 + dh]
                    + sm[(qgi*2 + 1)*1088 + r*68 + dh];
            o *= sInv[q];
            ctx[((size_t)(b_*SEQ + q0 + q))*DM + h*DH + dh] = o;
        }
    }

    // ---- normalization sweep: p = e_fp16 * (inv*16) -> gmem attn ----
    {
        const uint4* src = (const uint4*)(gE + ((size_t)bh*SEQ + q0)*SEQ);
        float* dst = attn_out + ((size_t)bh*SEQ + q0)*SEQ;
#pragma unroll 4
        for (int i = tid; i < 64*SEQ/8; i += 256) {   // 16384 uint4
            float inv = sInv[i >> 8] * 16.f;           // (i*8) >> 11
            uint4 raw = src[i];
            float2 f0 = __half22float2(*(const __half2*)&raw.x);
            float2 f1 = __half22float2(*(const __half2*)&raw.y);
            float2 f2 = __half22float2(*(const __half2*)&raw.z);
            float2 f3 = __half22float2(*(const __half2*)&raw.w);
            float4 p0 = make_float4(f0.x*inv, f0.y*inv, f1.x*inv, f1.y*inv);
            float4 p1 = make_float4(f2.x*inv, f2.y*inv, f3.x*inv, f3.y*inv);
            *(float4*)&dst[i*8]     = p0;
            *(float4*)&dst[i*8 + 4] = p1;
        }
    }
}

// ---------------------------------------------------------------------------
__global__ void ln_kernel(const float* __restrict__ x, float* __restrict__ out)
{
    __shared__ float red[16];
    const int row = blockIdx.x, tid = threadIdx.x;
    const float* xr = x + (size_t)row * DM;
    float4 d = ((const float4*)xr)[tid];
    float s  = d.x + d.y + d.z + d.w;
    float sq = d.x*d.x + d.y*d.y + d.z*d.z + d.w*d.w;
#pragma unroll
    for (int o = 16; o; o >>= 1) {
        s  += __shfl_xor_sync(0xffffffffu, s,  o);
        sq += __shfl_xor_sync(0xffffffffu, sq, o);
    }
    int warp = tid >> 5, lane = tid & 31;
    if (lane == 0) { red[warp] = s; red[warp + 8] = sq; }
    __syncthreads();
    float st = 0.f, sqt = 0.f;
#pragma unroll
    for (int i = 0; i < 8; i++) { st += red[i]; sqt += red[8 + i]; }
    float mean = st * (1.f/1024.f);
    float var  = sqt * (1.f/1024.f) - mean * mean;
    float rstd = rsqrtf(var + 1e-5f);
    float4 o;
    o.x = (d.x - mean) * rstd; o.y = (d.y - mean) * rstd;
    o.z = (d.z - mean) * rstd; o.w = (d.w - mean) * rstd;
    ((float4*)(out + (size_t)row * DM))[tid] = o;
}

// ---------------------------------------------------------------------------
extern "C" void kernel_launch(void* const* d_in, const int* in_sizes, int n_in,
                              void* d_out, int out_size)
{
    const float* iq  = (const float*)d_in[0];
    const float* ik  = (const float*)d_in[1];
    const float* iv  = (const float*)d_in[2];
    const float* wq  = (const float*)d_in[3];
    const float* wk  = (const float*)d_in[4];
    const float* wv  = (const float*)d_in[5];
    const float* wfc = (const float*)d_in[6];

    float* out  = (float*)d_out;
    float* attn = out + OUT_ELEMS;

    float *gq, *gk, *gv, *gctx, *gfc;
    __half* ge;
    cudaGetSymbolAddress((void**)&gq,   g_q);
    cudaGetSymbolAddress((void**)&gk,   g_k);
    cudaGetSymbolAddress((void**)&gv,   g_v);
    cudaGetSymbolAddress((void**)&gctx, g_ctx);
    cudaGetSymbolAddress((void**)&gfc,  g_fc);
    cudaGetSymbolAddress((void**)&ge,   g_e);

    size_t gemm_smem = (size_t)4 * 128 * KPAD * sizeof(unsigned);   // 81920 B
    cudaFuncSetAttribute(gemm_tf32, cudaFuncAttributeMaxDynamicSharedMemorySize, (int)gemm_smem);
    cudaFuncSetAttribute(gemm_qkv,  cudaFuncAttributeMaxDynamicSharedMemorySize, (int)gemm_smem);

    // merged Q/K/V projections: one launch, 3 problems via blockIdx.z
    QKVArgs qa;
    qa.X[0] = iq;  qa.X[1] = ik;  qa.X[2] = iv;
    qa.W[0] = wq;  qa.W[1] = wk;  qa.W[2] = wv;
    qa.Y[0] = gq;  qa.Y[1] = gk;  qa.Y[2] = gv;
    qa.mode[0] = 0; qa.mode[1] = 3; qa.mode[2] = 3;
    gemm_qkv<<<dim3(DM/128, MTOT/128, 3), 256, gemm_smem>>>(qa);

    size_t smem = (size_t)SM_ATT * sizeof(float);   // 90880 B
    cudaFuncSetAttribute(attn_kernel, cudaFuncAttributeMaxDynamicSharedMemorySize, (int)smem);
    attn_kernel<<<BATCH*NH*(SEQ/64), 256, smem>>>(gq, gk, gv, attn, gctx, ge);

    gemm_tf32<<<dim3(DM/128, MTOT/128), 256, gemm_smem>>>(gctx, wfc, iq, gfc, 1);
    ln_kernel<<<MTOT, 256>>>(gfc, out);
}

// round 17
// speedup vs baseline: 1.7178x; 1.1565x over previous
#include <cuda_runtime.h>
#include <cuda_fp16.h>
#include <math.h>

#define BATCH 4
#define SEQ   2048
#define DM    1024
#define NH    16
#define DH    64
#define MTOT  (BATCH*SEQ)
#define OUT_ELEMS ((size_t)MTOT*DM)

__device__ float  g_q[BATCH*NH*SEQ*DH];   // [b,h,s,d] raw fp32
__device__ __half g_k[BATCH*NH*SEQ*DH];   // [b,h,s,d''] fp16, 16-group interleaved d
__device__ float  g_v[BATCH*NH*SEQ*DH];   // [b,h,s,d] tf32-quantized values
__device__ float  g_ctx[MTOT*DM];
__device__ float  g_fc[MTOT*DM];
__device__ __half g_e[(size_t)BATCH*NH*SEQ*SEQ];   // unnormalized exp(s)/16

__device__ __forceinline__ unsigned f2tf(float x) {
    unsigned r;
    asm("cvt.rna.tf32.f32 %0, %1;" : "=r"(r) : "f"(x));
    return r;
}

__device__ __forceinline__ void mma8(float* c, const unsigned* a, unsigned b0, unsigned b1) {
    asm volatile(
        "mma.sync.aligned.m16n8k8.row.col.f32.tf32.tf32.f32 "
        "{%0,%1,%2,%3},{%4,%5,%6,%7},{%8,%9},{%0,%1,%2,%3};"
        : "+f"(c[0]), "+f"(c[1]), "+f"(c[2]), "+f"(c[3])
        : "r"(a[0]), "r"(a[1]), "r"(a[2]), "r"(a[3]), "r"(b0), "r"(b1));
}

__device__ __forceinline__ void mma16h(float* c, const unsigned* a, unsigned b0, unsigned b1) {
    asm volatile(
        "mma.sync.aligned.m16n8k16.row.col.f32.f16.f16.f32 "
        "{%0,%1,%2,%3},{%4,%5,%6,%7},{%8,%9},{%0,%1,%2,%3};"
        : "+f"(c[0]), "+f"(c[1]), "+f"(c[2]), "+f"(c[3])
        : "r"(a[0]), "r"(a[1]), "r"(a[2]), "r"(a[3]), "r"(b0), "r"(b1));
}

__device__ __forceinline__ void cpasync16(unsigned saddr, const void* g) {
    asm volatile("cp.async.cg.shared.global [%0], [%1], 16;" :: "r"(saddr), "l"(g));
}
__device__ __forceinline__ void cpasync_commit() {
    asm volatile("cp.async.commit_group;");
}
__device__ __forceinline__ void cpasync_wait0() {
    asm volatile("cp.async.wait_group 0;");
}

// ---------------------------------------------------------------------------
// Dense GEMM body: C = X[M,K] @ W[N,K]^T, tf32 mma, CTA 128x128, BK=16.
// mode 0: scatter fp32 [B,H,S,Dh] (Q); mode 1: +residual row-major (FC);
// mode 3: scatter tf32-quantized fp32 [B,H,S,Dh] (V);
// mode 5: scatter fp16 [B,H,S,Dh''] with 16-group interleave on dh (K).
// ---------------------------------------------------------------------------
#define KPAD 20

__device__ __forceinline__ void gemm_body(
    const float* __restrict__ X, const float* __restrict__ W,
    const float* __restrict__ resid, void* __restrict__ Yv, int mode,
    unsigned* gsm)
{
    unsigned (*As)[128][KPAD] = (unsigned(*)[128][KPAD])gsm;
    unsigned (*Bs)[128][KPAD] = (unsigned(*)[128][KPAD])(gsm + 2*128*KPAD);

    const int tid  = threadIdx.x;
    const int lane = tid & 31;
    const int warp = tid >> 5;
    const int warpM = warp >> 1;
    const int warpN = warp & 1;
    const int gid = lane >> 2;
    const int tig = lane & 3;

    const int ms = blockIdx.y * 128;
    const int ns = blockIdx.x * 128;
    const int lr = tid >> 2;
    const int lc = (tid & 3) * 4;

    float acc[2][8][4];
#pragma unroll
    for (int mt = 0; mt < 2; mt++)
#pragma unroll
        for (int nt = 0; nt < 8; nt++)
#pragma unroll
            for (int i = 0; i < 4; i++) acc[mt][nt][i] = 0.f;

    float4 px[2], pw[2];
#pragma unroll
    for (int h = 0; h < 2; h++) {
        int r = lr + h * 64;
        px[h] = *(const float4*)&X[(size_t)(ms + r) * DM + lc];
        pw[h] = *(const float4*)&W[(size_t)(ns + r) * DM + lc];
    }
#pragma unroll
    for (int h = 0; h < 2; h++) {
        int r = lr + h * 64;
        As[0][r][lc+0] = f2tf(px[h].x); As[0][r][lc+1] = f2tf(px[h].y);
        As[0][r][lc+2] = f2tf(px[h].z); As[0][r][lc+3] = f2tf(px[h].w);
        Bs[0][r][lc+0] = f2tf(pw[h].x); Bs[0][r][lc+1] = f2tf(pw[h].y);
        Bs[0][r][lc+2] = f2tf(pw[h].z); Bs[0][r][lc+3] = f2tf(pw[h].w);
    }
    __syncthreads();

    int buf = 0;
    for (int k0 = 0; k0 < DM; k0 += 16, buf ^= 1) {
        float4 nx[2], nw[2];
        const bool more = (k0 + 16 < DM);
        if (more) {
#pragma unroll
            for (int h = 0; h < 2; h++) {
                int r = lr + h * 64;
                nx[h] = *(const float4*)&X[(size_t)(ms + r) * DM + k0 + 16 + lc];
                nw[h] = *(const float4*)&W[(size_t)(ns + r) * DM + k0 + 16 + lc];
            }
        }

#pragma unroll
        for (int ks = 0; ks < 2; ks++) {
            const int kc = ks * 8 + tig;
            unsigned a[2][4];
#pragma unroll
            for (int mt = 0; mt < 2; mt++) {
                int base = warpM * 32 + mt * 16;
                a[mt][0] = As[buf][base + gid][kc];
                a[mt][1] = As[buf][base + gid + 8][kc];
                a[mt][2] = As[buf][base + gid][kc + 4];
                a[mt][3] = As[buf][base + gid + 8][kc + 4];
            }
#pragma unroll
            for (int nt = 0; nt < 8; nt++) {
                int cb = warpN * 64 + nt * 8 + gid;
                unsigned b0 = Bs[buf][cb][kc];
                unsigned b1 = Bs[buf][cb][kc + 4];
                mma8(acc[0][nt], a[0], b0, b1);
                mma8(acc[1][nt], a[1], b0, b1);
            }
        }

        if (more) {
            int nb = buf ^ 1;
#pragma unroll
            for (int h = 0; h < 2; h++) {
                int r = lr + h * 64;
                As[nb][r][lc+0] = f2tf(nx[h].x); As[nb][r][lc+1] = f2tf(nx[h].y);
                As[nb][r][lc+2] = f2tf(nx[h].z); As[nb][r][lc+3] = f2tf(nx[h].w);
                Bs[nb][r][lc+0] = f2tf(nw[h].x); Bs[nb][r][lc+1] = f2tf(nw[h].y);
                Bs[nb][r][lc+2] = f2tf(nw[h].z); Bs[nb][r][lc+3] = f2tf(nw[h].w);
            }
        }
        __syncthreads();
    }

    if (mode == 5) {
        __half* Yh = (__half*)Yv;
#pragma unroll
        for (int mt = 0; mt < 2; mt++) {
#pragma unroll
            for (int nt = 0; nt < 8; nt++) {
                int m0 = ms + warpM * 32 + mt * 16 + gid;
                int n_ = ns + warpN * 64 + nt * 8 + tig * 2;
                int b_ = m0 >> 11, s0 = m0 & 2047;
                int h  = n_ >> 6, dh = n_ & 63;
                int grp = dh & ~15, j = dh & 15;   // j even
                int pos = (j < 8) ? ((j >> 1) * 4) : (((j - 8) >> 1) * 4 + 2);
                size_t base = (((size_t)(b_*NH + h))*SEQ);
                __half2 v0 = __floats2half2_rn(acc[mt][nt][0], acc[mt][nt][1]);
                __half2 v1 = __floats2half2_rn(acc[mt][nt][2], acc[mt][nt][3]);
                *(__half2*)&Yh[(base + s0)*DH + grp + pos]     = v0;
                *(__half2*)&Yh[(base + s0 + 8)*DH + grp + pos] = v1;
            }
        }
        return;
    }

    float* Y = (float*)Yv;
#pragma unroll
    for (int mt = 0; mt < 2; mt++) {
#pragma unroll
        for (int nt = 0; nt < 8; nt++) {
#pragma unroll
            for (int i = 0; i < 4; i++) {
                int m = ms + warpM * 32 + mt * 16 + gid + (i >> 1) * 8;
                int n = ns + warpN * 64 + nt * 8 + tig * 2 + (i & 1);
                float v = acc[mt][nt][i];
                if (mode == 0) {
                    int b_ = m >> 11, s_ = m & 2047;
                    int h = n >> 6, dh = n & 63;
                    Y[(((size_t)(b_*NH + h))*SEQ + s_)*DH + dh] = v;
                } else if (mode == 3) {
                    int b_ = m >> 11, s_ = m & 2047;
                    int h = n >> 6, dh = n & 63;
                    Y[(((size_t)(b_*NH + h))*SEQ + s_)*DH + dh] = __uint_as_float(f2tf(v));
                } else {
                    Y[(size_t)m * DM + n] = v + resid[(size_t)m * DM + n];
                }
            }
        }
    }
}

// FC GEMM (mode 1)
__global__ void __launch_bounds__(256, 2)
gemm_tf32(const float* __restrict__ X, const float* __restrict__ W,
          const float* __restrict__ resid, float* __restrict__ Y, int mode)
{
    extern __shared__ unsigned gsm[];
    gemm_body(X, W, resid, Y, mode, gsm);
}

// Merged Q/K/V projections via blockIdx.z (packs wave tails of 3 launches)
struct QKVArgs {
    const float* X[3];
    const float* W[3];
    void*        Y[3];
    int          mode[3];
};

__global__ void __launch_bounds__(256, 2)
gemm_qkv(QKVArgs args)
{
    extern __shared__ unsigned gsm[];
    const int z = blockIdx.z;
    gemm_body(args.X[z], args.W[z], nullptr, args.Y[z], args.mode[z], gsm);
}

// ---------------------------------------------------------------------------
// Flash-style attention. CTA = (b,h, 64 q rows), 256 thr, 8 warps =
// 4 q-groups x 2 key-slices.
// QK: fp16 m16n8k16 mma, Q split hi/lo fp16 (lo pre-scaled by 2048), K fp16
//     with interleaved-d storage -> B fragments are single LDS.64,
//     stride 80 halves (40 words == 8 mod 32) -> conflict-free phases.
// PV: tf32 m16n8k8 (V tf32-quantized, R12 layout, stride 72).
// Double-buffered 64-key tiles via cp.async. e dumped fp16/16 coalesced;
// end sweep normalizes into attn_out.
// ---------------------------------------------------------------------------
#define AKT   64
#define NTIL  (SEQ/AKT)                    // 32
#define KSTRH 80                           // halves per K row
#define KBUF_B (AKT*KSTRH*2)               // 10240 bytes per K buf
#define SVSTR 72
#define VBUF_F (AKT*SVSTR)                 // 4608 floats per V buf
#define SMF_V  5120                        // float idx of V bufs (20480 B)
#define SESTR  36
#define SMF_E  14336                       // float idx of sE (57344 B)
#define SMF_SUM 18944
#define SMF_INV 19072
#define SM_ATT_BYTES 76800

__global__ void __launch_bounds__(256, 2)
attn_kernel(const float* __restrict__ gq, const __half* __restrict__ gk,
            const float* __restrict__ gv, float* __restrict__ attn_out,
            float* __restrict__ ctx, __half* __restrict__ gE)
{
    extern __shared__ float sm[];
    float* sSum = sm + SMF_SUM;
    float* sInv = sm + SMF_INV;

    const int tid  = threadIdx.x;
    const int lane = tid & 31;
    const int w    = tid >> 5;       // 0..7
    const int gid  = lane >> 2;      // 0..7
    const int tig  = lane & 3;       // 0..3
    const int qg   = w >> 1;         // 0..3
    const int ns   = w & 1;          // 0..1

    const int bid = blockIdx.x;
    const int qt  = bid & 31;
    const int bh  = bid >> 5;
    const int q0  = qt * 64;

    const float*  Qb = gq + (size_t)bh * SEQ * DH;
    const __half* Kb = gk + (size_t)bh * SEQ * DH;
    const float*  Vb = gv + (size_t)bh * SEQ * DH;

    const unsigned sbase = (unsigned)__cvta_generic_to_shared(sm);
    float* sEw = sm + SMF_E + w * 16 * SESTR;

    // staging: K 2 chunks/thread (512x16B), V 4 chunks/thread (1024x16B)
    // ---- prologue: stage tile 0 ----
#pragma unroll
    for (int i = 0; i < 2; i++) {
        int idx = tid + i * 256;          // 0..511
        int r = idx >> 3, c = (idx & 7) * 8;
        cpasync16(sbase + (unsigned)(r*KSTRH + c)*2, Kb + (size_t)r*DH + c);
    }
#pragma unroll
    for (int i = 0; i < 4; i++) {
        int idx = tid + i * 256;          // 0..1023
        int r = idx >> 4, c4 = (idx & 15) << 2;
        cpasync16(sbase + (unsigned)(SMF_V + r*SVSTR + c4)*4, Vb + (size_t)r*DH + c4);
    }
    cpasync_commit();

    // ---- Q fragments: fp16 hi/lo (lo scaled by 2048), scale 0.125 folded ----
    unsigned ahi[4][4], alo[4][4];
    {
        const float* Qr0 = Qb + (size_t)(q0 + qg*16 + gid) * DH;
        const float* Qr1 = Qr0 + (size_t)8 * DH;
        const int o0 = 2*tig, o1 = 2*tig + 8;
#pragma unroll
        for (int kc = 0; kc < 4; kc++) {
            const float* p0 = Qr0 + kc*16;
            const float* p1 = Qr1 + kc*16;
            float q00 = p0[o0]*0.125f,   q01 = p0[o0+1]*0.125f;
            float q10 = p1[o0]*0.125f,   q11 = p1[o0+1]*0.125f;
            float q02 = p0[o1]*0.125f,   q03 = p0[o1+1]*0.125f;
            float q12 = p1[o1]*0.125f,   q13 = p1[o1+1]*0.125f;
            __half2 h0 = __floats2half2_rn(q00, q01);
            __half2 h1 = __floats2half2_rn(q10, q11);
            __half2 h2 = __floats2half2_rn(q02, q03);
            __half2 h3 = __floats2half2_rn(q12, q13);
            float2 f0 = __half22float2(h0), f1 = __half22float2(h1);
            float2 f2 = __half22float2(h2), f3 = __half22float2(h3);
            __half2 l0 = __floats2half2_rn((q00-f0.x)*2048.f, (q01-f0.y)*2048.f);
            __half2 l1 = __floats2half2_rn((q10-f1.x)*2048.f, (q11-f1.y)*2048.f);
            __half2 l2 = __floats2half2_rn((q02-f2.x)*2048.f, (q03-f2.y)*2048.f);
            __half2 l3 = __floats2half2_rn((q12-f3.x)*2048.f, (q13-f3.y)*2048.f);
            ahi[kc][0] = *(unsigned*)&h0; ahi[kc][1] = *(unsigned*)&h1;
            ahi[kc][2] = *(unsigned*)&h2; ahi[kc][3] = *(unsigned*)&h3;
            alo[kc][0] = *(unsigned*)&l0; alo[kc][1] = *(unsigned*)&l1;
            alo[kc][2] = *(unsigned*)&l2; alo[kc][3] = *(unsigned*)&l3;
        }
    }

    float rsum0 = 0.f, rsum1 = 0.f;
    float acc2[8][4];
#pragma unroll
    for (int nd = 0; nd < 8; nd++)
#pragma unroll
        for (int i = 0; i < 4; i++) acc2[nd][i] = 0.f;

    // ================= main pass =================
    for (int t = 0; t < NTIL; t++) {
        const int buf = t & 1;
        const __half* sKh = (const __half*)sm + buf*(KBUF_B/2);
        const float*  sVb = sm + SMF_V + buf*VBUF_F;

        cpasync_wait0();
        __syncthreads();

        if (t + 1 < NTIL) {
            const int nb = (t + 1) & 1;
            const __half* Kn = Kb + (size_t)(t+1)*AKT*DH;
            const float*  Vn = Vb + (size_t)(t+1)*AKT*DH;
#pragma unroll
            for (int i = 0; i < 2; i++) {
                int idx = tid + i * 256;
                int r = idx >> 3, c = (idx & 7) * 8;
                cpasync16(sbase + (unsigned)(nb*KBUF_B) + (unsigned)(r*KSTRH + c)*2,
                          Kn + (size_t)r*DH + c);
            }
#pragma unroll
            for (int i = 0; i < 4; i++) {
                int idx = tid + i * 256;
                int r = idx >> 4, c4 = (idx & 15) << 2;
                cpasync16(sbase + (unsigned)(SMF_V + nb*VBUF_F + r*SVSTR + c4)*4,
                          Vn + (size_t)r*DH + c4);
            }
            cpasync_commit();
        }

        // ---- QK (fp16 2-step) + exp + e staging ----
#pragma unroll
        for (int n8 = 0; n8 < 4; n8++) {
            const int n0 = ns * 32 + n8 * 8;
            float ah[4] = {0.f, 0.f, 0.f, 0.f};
            float al[4] = {0.f, 0.f, 0.f, 0.f};
#pragma unroll
            for (int kc = 0; kc < 4; kc++) {
                uint2 b = *(const uint2*)(sKh + (n0 + gid)*KSTRH + kc*16 + tig*4);
                mma16h(ah, ahi[kc], b.x, b.y);
                mma16h(al, alo[kc], b.x, b.y);
            }
            float a0 = __expf(ah[0] + al[0]*(1.f/2048.f));
            float a1 = __expf(ah[1] + al[1]*(1.f/2048.f));
            float a2 = __expf(ah[2] + al[2]*(1.f/2048.f));
            float a3 = __expf(ah[3] + al[3]*(1.f/2048.f));
            rsum0 += a0 + a1;
            rsum1 += a2 + a3;
            sEw[gid*SESTR + n8*8 + 2*tig]       = __uint_as_float(f2tf(a0));
            sEw[gid*SESTR + n8*8 + 2*tig + 1]   = __uint_as_float(f2tf(a1));
            sEw[(gid+8)*SESTR + n8*8 + 2*tig]   = __uint_as_float(f2tf(a2));
            sEw[(gid+8)*SESTR + n8*8 + 2*tig+1] = __uint_as_float(f2tf(a3));
        }
        __syncwarp();

        // ---- PV over this warp's 32 keys (tf32) ----
#pragma unroll
        for (int k8 = 0; k8 < 4; k8++) {
            unsigned a[4];
            a[0] = __float_as_uint(sEw[gid*SESTR + k8*8 + tig]);
            a[1] = __float_as_uint(sEw[(gid+8)*SESTR + k8*8 + tig]);
            a[2] = __float_as_uint(sEw[gid*SESTR + k8*8 + tig + 4]);
            a[3] = __float_as_uint(sEw[(gid+8)*SESTR + k8*8 + tig + 4]);
            const int kr = ns * 32 + k8 * 8;
#pragma unroll
            for (int nd = 0; nd < 8; nd++) {
                unsigned b0 = __float_as_uint(sVb[(kr + tig)*SVSTR + nd*8 + gid]);
                unsigned b1 = __float_as_uint(sVb[(kr + tig + 4)*SVSTR + nd*8 + gid]);
                mma8(acc2[nd], a, b0, b1);
            }
        }

        // ---- e dump: sEw (16x32) -> gE fp16 (scaled 1/16), coalesced ----
        {
            const int r0 = lane >> 2;            // 0..7
            const int c8 = (lane & 3) * 8;       // 0,8,16,24
#pragma unroll
            for (int rg = 0; rg < 16; rg += 8) {
                const float* s = &sEw[(rg + r0)*SESTR + c8];
                float4 v0 = *(const float4*)&s[0];
                float4 v1 = *(const float4*)&s[4];
                __half2 h0 = __floats2half2_rn(v0.x*0.0625f, v0.y*0.0625f);
                __half2 h1 = __floats2half2_rn(v0.z*0.0625f, v0.w*0.0625f);
                __half2 h2 = __floats2half2_rn(v1.x*0.0625f, v1.y*0.0625f);
                __half2 h3 = __floats2half2_rn(v1.z*0.0625f, v1.w*0.0625f);
                uint4 pk;
                pk.x = *(const unsigned*)&h0;
                pk.y = *(const unsigned*)&h1;
                pk.z = *(const unsigned*)&h2;
                pk.w = *(const unsigned*)&h3;
                *(uint4*)&gE[((size_t)bh*SEQ + q0 + qg*16 + rg + r0)*SEQ
                             + t*AKT + ns*32 + c8] = pk;
            }
        }
    }

    // ---- row-sum reduction ----
    rsum0 += __shfl_xor_sync(0xffffffffu, rsum0, 1);
    rsum0 += __shfl_xor_sync(0xffffffffu, rsum0, 2);
    rsum1 += __shfl_xor_sync(0xffffffffu, rsum1, 1);
    rsum1 += __shfl_xor_sync(0xffffffffu, rsum1, 2);
    if (tig == 0) {
        sSum[w*16 + gid]     = rsum0;
        sSum[w*16 + gid + 8] = rsum1;
    }
    __syncthreads();
    if (tid < 64) {
        int qgq = tid >> 4, r = tid & 15;
        float s = sSum[(qgq*2)*16 + r] + sSum[(qgq*2 + 1)*16 + r];
        sInv[tid] = 1.f / s;
    }
    // ---- O partial stage into retired K/V buffer region (stride 68) ----
    {
        float* sOw = sm + w * 1088;    // 16*68 per warp, 8704 floats total
#pragma unroll
        for (int nd = 0; nd < 8; nd++) {
            sOw[gid*68 + nd*8 + 2*tig]       = acc2[nd][0];
            sOw[gid*68 + nd*8 + 2*tig + 1]   = acc2[nd][1];
            sOw[(gid+8)*68 + nd*8 + 2*tig]   = acc2[nd][2];
            sOw[(gid+8)*68 + nd*8 + 2*tig+1] = acc2[nd][3];
        }
    }
    __syncthreads();

    // ---- ctx write ----
    {
        const int b_ = bh >> 4, h = bh & 15;
#pragma unroll
        for (int i = 0; i < 16; i++) {
            int idx = tid + i * 256;             // 0..4095
            int q = idx >> 6, dh = idx & 63;
            int qgi = q >> 4, r = q & 15;
            float o = sm[(qgi*2)*1088 + r*68 + dh]
                    + sm[(qgi*2 + 1)*1088 + r*68 + dh];
            o *= sInv[q];
            ctx[((size_t)(b_*SEQ + q0 + q))*DM + h*DH + dh] = o;
        }
    }

    // ---- normalization sweep: p = e_fp16 * (inv*16) -> gmem attn ----
    {
        const uint4* src = (const uint4*)(gE + ((size_t)bh*SEQ + q0)*SEQ);
        float* dst = attn_out + ((size_t)bh*SEQ + q0)*SEQ;
#pragma unroll 4
        for (int i = tid; i < 64*SEQ/8; i += 256) {   // 16384 uint4
            float inv = sInv[i >> 8] * 16.f;           // (i*8) >> 11
            uint4 raw = src[i];
            float2 f0 = __half22float2(*(const __half2*)&raw.x);
            float2 f1 = __half22float2(*(const __half2*)&raw.y);
            float2 f2 = __half22float2(*(const __half2*)&raw.z);
            float2 f3 = __half22float2(*(const __half2*)&raw.w);
            float4 p0 = make_float4(f0.x*inv, f0.y*inv, f1.x*inv, f1.y*inv);
            float4 p1 = make_float4(f2.x*inv, f2.y*inv, f3.x*inv, f3.y*inv);
            *(float4*)&dst[i*8]     = p0;
            *(float4*)&dst[i*8 + 4] = p1;
        }
    }
}

// ---------------------------------------------------------------------------
__global__ void ln_kernel(const float* __restrict__ x, float* __restrict__ out)
{
    __shared__ float red[16];
    const int row = blockIdx.x, tid = threadIdx.x;
    const float* xr = x + (size_t)row * DM;
    float4 d = ((const float4*)xr)[tid];
    float s  = d.x + d.y + d.z + d.w;
    float sq = d.x*d.x + d.y*d.y + d.z*d.z + d.w*d.w;
#pragma unroll
    for (int o = 16; o; o >>= 1) {
        s  += __shfl_xor_sync(0xffffffffu, s,  o);
        sq += __shfl_xor_sync(0xffffffffu, sq, o);
    }
    int warp = tid >> 5, lane = tid & 31;
    if (lane == 0) { red[warp] = s; red[warp + 8] = sq; }
    __syncthreads();
    float st = 0.f, sqt = 0.f;
#pragma unroll
    for (int i = 0; i < 8; i++) { st += red[i]; sqt += red[8 + i]; }
    float mean = st * (1.f/1024.f);
    float var  = sqt * (1.f/1024.f) - mean * mean;
    float rstd = rsqrtf(var + 1e-5f);
    float4 o;
    o.x = (d.x - mean) * rstd; o.y = (d.y - mean) * rstd;
    o.z = (d.z - mean) * rstd; o.w = (d.w - mean) * rstd;
    ((float4*)(out + (size_t)row * DM))[tid] = o;
}

// ---------------------------------------------------------------------------
extern "C" void kernel_launch(void* const* d_in, const int* in_sizes, int n_in,
                              void* d_out, int out_size)
{
    const float* iq  = (const float*)d_in[0];
    const float* ik  = (const float*)d_in[1];
    const float* iv  = (const float*)d_in[2];
    const float* wq  = (const float*)d_in[3];
    const float* wk  = (const float*)d_in[4];
    const float* wv  = (const float*)d_in[5];
    const float* wfc = (const float*)d_in[6];

    float* out  = (float*)d_out;
    float* attn = out + OUT_ELEMS;

    float *gq, *gv, *gctx, *gfc;
    __half *gk, *ge;
    cudaGetSymbolAddress((void**)&gq,   g_q);
    cudaGetSymbolAddress((void**)&gk,   g_k);
    cudaGetSymbolAddress((void**)&gv,   g_v);
    cudaGetSymbolAddress((void**)&gctx, g_ctx);
    cudaGetSymbolAddress((void**)&gfc,  g_fc);
    cudaGetSymbolAddress((void**)&ge,   g_e);

    size_t gemm_smem = (size_t)4 * 128 * KPAD * sizeof(unsigned);   // 81920 B
    cudaFuncSetAttribute(gemm_tf32, cudaFuncAttributeMaxDynamicSharedMemorySize, (int)gemm_smem);
    cudaFuncSetAttribute(gemm_qkv,  cudaFuncAttributeMaxDynamicSharedMemorySize, (int)gemm_smem);

    QKVArgs qa;
    qa.X[0] = iq;  qa.X[1] = ik;  qa.X[2] = iv;
    qa.W[0] = wq;  qa.W[1] = wk;  qa.W[2] = wv;
    qa.Y[0] = gq;  qa.Y[1] = gk;  qa.Y[2] = gv;
    qa.mode[0] = 0; qa.mode[1] = 5; qa.mode[2] = 3;
    gemm_qkv<<<dim3(DM/128, MTOT/128, 3), 256, gemm_smem>>>(qa);

    cudaFuncSetAttribute(attn_kernel, cudaFuncAttributeMaxDynamicSharedMemorySize, SM_ATT_BYTES);
    attn_kernel<<<BATCH*NH*(SEQ/64), 256, SM_ATT_BYTES>>>(gq, gk, gv, attn, gctx, ge);

    gemm_tf32<<<dim3(DM/128, MTOT/128), 256, gemm_smem>>>(gctx, wfc, iq, gfc, 1);
    ln_kernel<<<MTOT, 256>>>(gfc, out);
}